// round 6
// baseline (speedup 1.0000x reference)
#include <cuda_runtime.h>
#include <cuda_fp16.h>
#include <cstdint>

#define NN 100000
#define EE 1600000
#define HF 128           // HEADS * OUT_F
#define NB_SCAN 98       // ceil(NN/1024)
#define ROWS_B 48        // rows per gemm block
#define NGEMM 2084       // ceil(NN/48)
#define NCOUNT 6250      // ceil(EE/256)

// ---------------- scratch ----------------
__device__ unsigned int g_hh[NN * 64];  // 25.6 MB : h in half2 (64 x uint per row)
__device__ float g_asrc[NN * 4];
__device__ float g_adst[NN * 4];
__device__ int   g_deg[NN];
__device__ int   g_cursor[NN];
__device__ int   g_rowstart[NN + 1];
__device__ int   g_srcs[EE + NN];
__device__ int   g_bsums[NB_SCAN];
__device__ int   g_is64;

// ---------------- packed fp32x2 helpers ----------------
__device__ __forceinline__ unsigned long long pack2(float lo, float hi) {
    unsigned long long r;
    asm("mov.b64 %0, {%1, %2};" : "=l"(r) : "f"(lo), "f"(hi));
    return r;
}
__device__ __forceinline__ void unpack2(unsigned long long v, float& lo, float& hi) {
    asm("mov.b64 {%0, %1}, %2;" : "=f"(lo), "=f"(hi) : "l"(v));
}
#define FFMA2(acc, a, b) asm("fma.rn.f32x2 %0, %1, %2, %0;" : "+l"(acc) : "l"(a), "l"(b))

// ---------------- kernel 1: dtype detect + deg init ----------------
__global__ void init_kernel(const int* ei32) {
    if (blockIdx.x == 0) {
        __shared__ int nz;
        if (threadIdx.x == 0) nz = 0;
        __syncthreads();
        if (ei32[threadIdx.x * 2 + 1] != 0) atomicAdd(&nz, 1);
        __syncthreads();
        if (threadIdx.x == 0) g_is64 = (nz == 0) ? 1 : 0;
    }
    int i = blockIdx.x * blockDim.x + threadIdx.x;
    if (i < NN) g_deg[i] = 0;
}

// ---------------- kernel 2: GEMM (+att epilogue, fp16 h store) + degree count ----
// gemm blocks: 48 rows, 8 warps x 6 rows; lane owns cols [lane*4, lane*4+4)
// x staged DUPLICATED in smem: xs[(row*HF + k)*2 + {0,1}] = x[row][k] twice
__global__ __launch_bounds__(256, 3) void gemm_count_kernel(
    const float* __restrict__ x, const float* __restrict__ W,
    const float* __restrict__ att_src, const float* __restrict__ att_dst,
    const void* __restrict__ eiv) {
    if (blockIdx.x >= NGEMM) {
        int t = (blockIdx.x - NGEMM) * 256 + threadIdx.x;
        if (t < EE) {
            int dst;
            if (g_is64) dst = (int)((const long long*)eiv)[EE + t];
            else        dst = ((const int*)eiv)[EE + t];
            atomicAdd(&g_deg[dst], 1);
        }
        return;
    }

    __shared__ float xs[ROWS_B * HF * 2];  // 48 KB, duplicated broadcast layout
    const int warp = threadIdx.x >> 5;
    const int lane = threadIdx.x & 31;
    const int blk_row0 = blockIdx.x * ROWS_B;

    // stage: each thread handles 6 float4 reads -> 24 duplicated float2 writes
#pragma unroll
    for (int it = 0; it < 6; it++) {
        int idx = it * 256 + threadIdx.x;         // float4 index, 1536 total
        int row = idx >> 5, c4 = (idx & 31) * 4;
        float4 v = make_float4(0.f, 0.f, 0.f, 0.f);
        if (blk_row0 + row < NN) v = *(const float4*)(x + (size_t)(blk_row0 + row) * HF + c4);
        float* p = xs + (row * HF + c4) * 2;
        p[0] = v.x; p[1] = v.x; p[2] = v.y; p[3] = v.y;
        p[4] = v.z; p[5] = v.z; p[6] = v.w; p[7] = v.w;
    }
    __syncthreads();

    const float* xw = xs + warp * 6 * HF * 2;   // this warp's 6 rows
    unsigned long long acc01[6], acc23[6];
    const unsigned long long z = pack2(0.f, 0.f);
#pragma unroll
    for (int r = 0; r < 6; r++) { acc01[r] = z; acc23[r] = z; }

#pragma unroll 4
    for (int k = 0; k < HF; k += 2) {
        float4 w0 = *(const float4*)(W + k * HF + lane * 4);
        float4 w1 = *(const float4*)(W + (k + 1) * HF + lane * 4);
        unsigned long long w0_01 = pack2(w0.x, w0.y), w0_23 = pack2(w0.z, w0.w);
        unsigned long long w1_01 = pack2(w1.x, w1.y), w1_23 = pack2(w1.z, w1.w);
#pragma unroll
        for (int r = 0; r < 6; r++) {
            ulonglong2 s = *(const ulonglong2*)(xw + (r * HF + k) * 2);  // (xk,xk | xk1,xk1)
            FFMA2(acc01[r], s.x, w0_01);
            FFMA2(acc23[r], s.x, w0_23);
            FFMA2(acc01[r], s.y, w1_01);
            FFMA2(acc23[r], s.y, w1_23);
        }
    }

    const int head = lane >> 3;
    const int fo   = (lane & 7) * 4;
    float4 s4 = *(const float4*)(att_src + head * 32 + fo);
    float4 d4 = *(const float4*)(att_dst + head * 32 + fo);

#pragma unroll
    for (int r = 0; r < 6; r++) {
        int row = blk_row0 + warp * 6 + r;
        if (row >= NN) continue;
        float4 a;
        unpack2(acc01[r], a.x, a.y);
        unpack2(acc23[r], a.z, a.w);
        // store fp16 message copy
        half2 h01 = __floats2half2_rn(a.x, a.y);
        half2 h23 = __floats2half2_rn(a.z, a.w);
        uint2 hp;
        hp.x = *(unsigned int*)&h01;
        hp.y = *(unsigned int*)&h23;
        *(uint2*)(g_hh + (size_t)row * 64 + lane * 2) = hp;
        // attention logits in fp32 (exact)
        float ps = a.x * s4.x + a.y * s4.y + a.z * s4.z + a.w * s4.w;
        float pd = a.x * d4.x + a.y * d4.y + a.z * d4.z + a.w * d4.w;
#pragma unroll
        for (int o = 1; o < 8; o <<= 1) {
            ps += __shfl_xor_sync(0xFFFFFFFFu, ps, o);
            pd += __shfl_xor_sync(0xFFFFFFFFu, pd, o);
        }
        if ((lane & 7) == 0) {
            g_asrc[row * 4 + head] = ps;
            g_adst[row * 4 + head] = pd;
        }
    }
}

// ---------------- CSR scan (2 kernels) ----------------
__global__ void scan_block_kernel() {
    __shared__ int sm[1024];
    int i = blockIdx.x * 1024 + threadIdx.x;
    int v = (i < NN) ? (g_deg[i] + 1) : 0;  // +1 self loop
    sm[threadIdx.x] = v;
    __syncthreads();
    for (int o = 1; o < 1024; o <<= 1) {
        int t = (threadIdx.x >= (unsigned)o) ? sm[threadIdx.x - o] : 0;
        __syncthreads();
        sm[threadIdx.x] += t;
        __syncthreads();
    }
    if (i < NN) g_rowstart[i] = sm[threadIdx.x] - v;  // exclusive within block
    if (threadIdx.x == 1023) g_bsums[blockIdx.x] = sm[1023];
}

// adds global block offset (re-scanning the 98 partials locally) + seeds cursor
__global__ void scan_add_kernel() {
    __shared__ int sp[NB_SCAN];
    if (threadIdx.x < NB_SCAN) sp[threadIdx.x] = g_bsums[threadIdx.x];
    __syncthreads();
    if (threadIdx.x == 0) {  // tiny serial scan in smem (98 iters, ~400 cyc)
        int acc = 0;
        for (int b = 0; b <= (int)blockIdx.x && b < NB_SCAN; b++) {
            int v = sp[b]; sp[b] = acc; acc += v;
        }
    }
    __syncthreads();
    int off = sp[blockIdx.x];
    int i = blockIdx.x * 1024 + threadIdx.x;
    if (i < NN) {
        int rs = g_rowstart[i] + off;
        g_rowstart[i] = rs;
        g_cursor[i]   = rs;   // scatter cursor starts at row base
    }
    if (blockIdx.x == 0 && threadIdx.x == 0) g_rowstart[NN] = EE + NN;
}

__global__ void scatter_kernel(const void* eiv) {
    int t = blockIdx.x * blockDim.x + threadIdx.x;
    if (t >= EE + NN) return;
    int s, d;
    if (t < EE) {
        if (g_is64) {
            s = (int)((const long long*)eiv)[t];
            d = (int)((const long long*)eiv)[EE + t];
        } else {
            s = ((const int*)eiv)[t];
            d = ((const int*)eiv)[EE + t];
        }
    } else {
        s = d = t - EE;  // self loop
    }
    int p = atomicAdd(&g_cursor[d], 1);
    g_srcs[p] = s;
}

// ---------------- per-destination softmax + aggregation (fp16 gather) --------
__global__ __launch_bounds__(256) void aggregate_kernel(
    const float* __restrict__ bias, float* __restrict__ out) {
    const int warp = threadIdx.x >> 5;
    const int lane = threadIdx.x & 31;
    const int i = blockIdx.x * 8 + warp;
    if (i >= NN) return;

    const int head = lane >> 3;
    const float adst = g_adst[i * 4 + head];
    const int start = g_rowstart[i];
    const int end   = g_rowstart[i + 1];

    float4 acc = make_float4(0.f, 0.f, 0.f, 0.f);
    float ssum = 0.f;

    int src_next = g_srcs[start];
    for (int j = start; j < end; j++) {
        int src = src_next;
        if (j + 1 < end) src_next = g_srcs[j + 1];
        float e = g_asrc[src * 4 + head] + adst;
        e = (e > 0.f) ? e : 0.2f * e;
        float w = __expf(e);
        uint2 hp = *(const uint2*)(g_hh + (size_t)src * 64 + lane * 2);
        float2 f01 = __half22float2(*(const half2*)&hp.x);
        float2 f23 = __half22float2(*(const half2*)&hp.y);
        ssum += w;
        acc.x += w * f01.x;
        acc.y += w * f01.y;
        acc.z += w * f23.x;
        acc.w += w * f23.y;
    }

    float inv = 1.f / ssum;
    float4 b = *(const float4*)(bias + lane * 4);
    float4 o;
    o.x = acc.x * inv + b.x;
    o.y = acc.y * inv + b.y;
    o.z = acc.z * inv + b.z;
    o.w = acc.w * inv + b.w;
    *(float4*)(out + (size_t)i * HF + lane * 4) = o;
}

// ---------------- launch ----------------
extern "C" void kernel_launch(void* const* d_in, const int* in_sizes, int n_in,
                              void* d_out, int out_size) {
    const float* x    = (const float*)d_in[0];
    const void*  ei   = d_in[1];
    const float* W    = (const float*)d_in[2];
    const float* asv  = (const float*)d_in[3];
    const float* adv  = (const float*)d_in[4];
    const float* bias = (const float*)d_in[5];
    float* out = (float*)d_out;

    init_kernel<<<(NN + 255) / 256, 256>>>((const int*)ei);
    gemm_count_kernel<<<NGEMM + NCOUNT, 256>>>(x, W, asv, adv, ei);
    scan_block_kernel<<<NB_SCAN, 1024>>>();
    scan_add_kernel<<<NB_SCAN, 1024>>>();
    scatter_kernel<<<(EE + NN + 255) / 256, 256>>>(ei);
    aggregate_kernel<<<(NN + 7) / 8, 256>>>(bias, out);
}